// round 9
// baseline (speedup 1.0000x reference)
#include <cuda_runtime.h>
#include <cstdint>

static constexpr int E_   = 32;
static constexpr int H_   = 2048;
static constexpr int I_   = 768;
static constexpr int T_   = 2048;
static constexpr int MAXA = 8192;

// tf32 truncation-bias correction (validated R2-R7)
static constexpr float CBIAS = 1.000704f;

// ---------------- scratch ----------------------------------------------------
__device__ int   g_counts[E_];
__device__ int   g_offsets[E_];
__device__ int   g_total;
__device__ int   g_tok[MAXA];
__device__ float g_w[MAXA];
__device__ int   g_inv[T_ * 4];
__device__ float g_act[(size_t)MAXA * I_];
__device__ float g_dout[(size_t)MAXA * H_];

__device__ __forceinline__ uint32_t smem_u32(const void* p) {
    uint32_t a;
    asm("{ .reg .u64 t; cvta.to.shared.u64 t, %1; cvt.u32.u64 %0, t; }" : "=r"(a) : "l"(p));
    return a;
}
__device__ __forceinline__ void cpa16(uint32_t dst, const void* src) {
    asm volatile("cp.async.cg.shared.global [%0], [%1], 16;" :: "r"(dst), "l"(src));
}

// ---------------- routing (known-good) ----------------------------------------
__global__ void route_kernel(const int* __restrict__ ridx,
                             const float* __restrict__ rw) {
    __shared__ int s_cnt[E_], s_cur[E_], s_off[E_];
    int tid = threadIdx.x;
    if (tid < E_) { s_cnt[tid] = 0; s_cur[tid] = 0; }
    __syncthreads();
    for (int t = tid; t < T_; t += blockDim.x) {
        int e0 = ridx[4*t], e1 = ridx[4*t+1], e2 = ridx[4*t+2], e3 = ridx[4*t+3];
        if (e0 != e1 && e0 != e2 && e0 != e3) atomicAdd(&s_cnt[e0], 1);
        if (e1 != e2 && e1 != e3)             atomicAdd(&s_cnt[e1], 1);
        if (e2 != e3)                          atomicAdd(&s_cnt[e2], 1);
        atomicAdd(&s_cnt[e3], 1);
    }
    __syncthreads();
    if (tid == 0) {
        int acc = 0;
        for (int e = 0; e < E_; e++) {
            s_off[e] = acc; g_offsets[e] = acc; g_counts[e] = s_cnt[e];
            acc += s_cnt[e];
        }
        g_total = acc;
    }
    __syncthreads();
    for (int t = tid; t < T_; t += blockDim.x) {
        int ee[4]; float ww[4];
        #pragma unroll
        for (int k = 0; k < 4; k++) { ee[k] = ridx[4*t+k]; ww[k] = rw[4*t+k]; }
        #pragma unroll
        for (int k = 0; k < 4; k++) {
            bool keep = true;
            #pragma unroll
            for (int j = k + 1; j < 4; j++) if (ee[j] == ee[k]) keep = false;
            int pos = -1;
            if (keep) {
                pos = s_off[ee[k]] + atomicAdd(&s_cur[ee[k]], 1);
                g_tok[pos] = t; g_w[pos] = ww[k];
            }
            g_inv[4*t + k] = pos;
        }
    }
}

// ---------------- grouped GEMM: 128x256 tile, 16 warps of 32x(32|64), 4-stage --
// 512 threads -> 16 warps/SM (4 per SMSP) for latency hiding; acc=64 regs/thread.
// FIRST: A = gathered hidden [cnt,2048]; B smem = gate[0:128)|up[128:256);
//        epilogue = SwiGLU -> g_act[.., n0..n0+128)
// else : A = g_act [cnt,768]; B smem = 256 n-cols; epilogue *w -> g_dout
static constexpr int AS_STRIDE = 36;
static constexpr int AS_BUF    = 128 * AS_STRIDE;   // 4608 u32
static constexpr int BS_STRIDE = 264;
static constexpr int BS_BUF    = 32 * BS_STRIDE;    // 8448 u32
static constexpr int STG       = AS_BUF + BS_BUF;   // 13056 u32 = 52224 B
static constexpr int SMEM_BYTES = 4 * STG * 4;      // 208896 B

template<int KDIM, bool FIRST>
__global__ void __launch_bounds__(512, 1)
moe_gemm(const float* __restrict__ Ain, const float* __restrict__ Bfull) {
    constexpr int NCH    = KDIM / 32;
    constexpr int LDB    = FIRST ? 1536 : 2048;
    constexpr int ROWSPE = FIRST ? 2048 : 768;
    constexpr int NOUT   = FIRST ? 128 : 256;

    extern __shared__ uint32_t sm[];
    const int e   = blockIdx.z;
    const int cnt = g_counts[e];
    const int m0  = blockIdx.x * 128;   // m fastest
    if (m0 >= cnt) return;
    const int off = g_offsets[e];
    const int n0  = blockIdx.y * NOUT;
    const int tid = threadIdx.x;
    const int wid = tid >> 5, lane = tid & 31;
    const uint32_t sbase = smem_u32(sm);

    // ---- A staging: 2 rows/thread, row = p*64 + (tid>>3), seg = tid&7 ----
    const int a_seg = tid & 7;
    const int a_r   = tid >> 3;          // 0..63
    const float* aSrc[2];
    uint32_t aDst[2];
    #pragma unroll
    for (int p = 0; p < 2; p++) {
        int gm = m0 + p * 64 + a_r;
        int rr = (gm < cnt) ? gm : 0;
        aSrc[p] = (FIRST ? Ain + (size_t)g_tok[off + rr] * KDIM
                         : g_act + (size_t)(off + rr) * KDIM) + a_seg * 4;
        aDst[p] = sbase + (uint32_t)((p * 64 + a_r) * AS_STRIDE + a_seg * 4) * 4;
    }
    // ---- B staging: 4 segs/thread; row = tid>>4, seg16 = (tid&15)+16p ----
    const int b_r = tid >> 4;            // 0..31
    const float* bSrc[4];
    uint32_t bDst[4];
    #pragma unroll
    for (int p = 0; p < 4; p++) {
        int col  = ((tid & 15) + 16 * p) * 4;        // 0..255 (u32 col in smem)
        int gcol = FIRST ? (col < 128 ? n0 + col : 768 + n0 + (col - 128))
                         : n0 + col;
        bSrc[p] = Bfull + ((size_t)e * ROWSPE + b_r) * LDB + gcol;
        bDst[p] = sbase + (uint32_t)(AS_BUF + b_r * BS_STRIDE + col) * 4;
    }

    float acc[2][8][4];
    #pragma unroll
    for (int i = 0; i < 2; i++)
        #pragma unroll
        for (int j = 0; j < 8; j++)
            #pragma unroll
            for (int k = 0; k < 4; k++) acc[i][j][k] = 0.f;

    const int wm = (wid >> 2) * 32;                 // 0/32/64/96
    const int wn = (wid & 3) * (FIRST ? 32 : 64);
    const int qr = lane >> 2;
    const int qk = lane & 3;

    auto load_chunk = [&](int c) {
        const uint32_t so = (uint32_t)(c & 3) * (STG * 4);
        const size_t akc = (size_t)c * 32;
        #pragma unroll
        for (int p = 0; p < 2; p++) cpa16(aDst[p] + so, aSrc[p] + akc);
        const size_t bkc = (size_t)c * 32 * LDB;
        #pragma unroll
        for (int p = 0; p < 4; p++) cpa16(bDst[p] + so, bSrc[p] + bkc);
        asm volatile("cp.async.commit_group;" ::: "memory");
    };

    load_chunk(0); load_chunk(1); load_chunk(2);

    for (int c = 0; c < NCH; c++) {
        int rem = NCH - 1 - c;
        if (rem >= 2)      asm volatile("cp.async.wait_group 2;" ::: "memory");
        else if (rem == 1) asm volatile("cp.async.wait_group 1;" ::: "memory");
        else               asm volatile("cp.async.wait_group 0;" ::: "memory");
        __syncthreads();
        if (c + 3 < NCH) load_chunk(c + 3);

        const uint32_t* As = sm + (c & 3) * STG;
        const uint32_t* Bs = As + AS_BUF;
        #pragma unroll
        for (int kk = 0; kk < 32; kk += 8) {
            uint32_t af[2][4], bf[8][2];
            #pragma unroll
            for (int mi = 0; mi < 2; mi++) {
                int mr = wm + mi * 16 + qr;
                af[mi][0] = As[mr * AS_STRIDE + kk + qk];
                af[mi][1] = As[(mr + 8) * AS_STRIDE + kk + qk];
                af[mi][2] = As[mr * AS_STRIDE + kk + qk + 4];
                af[mi][3] = As[(mr + 8) * AS_STRIDE + kk + qk + 4];
            }
            #pragma unroll
            for (int ni = 0; ni < 8; ni++) {
                int nc = FIRST ? (ni < 4 ? wn + ni * 8 + qr : 128 + wn + (ni - 4) * 8 + qr)
                               : wn + ni * 8 + qr;
                bf[ni][0] = Bs[(kk + qk) * BS_STRIDE + nc];
                bf[ni][1] = Bs[(kk + qk + 4) * BS_STRIDE + nc];
            }
            #pragma unroll
            for (int mi = 0; mi < 2; mi++)
                #pragma unroll
                for (int ni = 0; ni < 8; ni++)
                    asm volatile(
                        "mma.sync.aligned.m16n8k8.row.col.f32.tf32.tf32.f32 "
                        "{%0,%1,%2,%3}, {%4,%5,%6,%7}, {%8,%9}, {%0,%1,%2,%3};"
                        : "+f"(acc[mi][ni][0]), "+f"(acc[mi][ni][1]),
                          "+f"(acc[mi][ni][2]), "+f"(acc[mi][ni][3])
                        : "r"(af[mi][0]), "r"(af[mi][1]),
                          "r"(af[mi][2]), "r"(af[mi][3]),
                          "r"(bf[ni][0]), "r"(bf[ni][1]));
        }
        __syncthreads();
    }

    // ---- epilogue ----
    #pragma unroll
    for (int mi = 0; mi < 2; mi++) {
        #pragma unroll
        for (int half = 0; half < 2; half++) {
            int r  = wm + mi * 16 + qr + half * 8;
            int gm = m0 + r;
            if (gm >= cnt) continue;
            if (FIRST) {
                float* rowp = g_act + (size_t)(off + gm) * I_ + n0;
                #pragma unroll
                for (int ni = 0; ni < 4; ni++) {
                    int nc = wn + ni * 8 + qk * 2;
                    float g0 = acc[mi][ni][half * 2 + 0] * CBIAS;
                    float g1 = acc[mi][ni][half * 2 + 1] * CBIAS;
                    float u0 = acc[mi][ni + 4][half * 2 + 0] * CBIAS;
                    float u1 = acc[mi][ni + 4][half * 2 + 1] * CBIAS;
                    float v0 = u0 * (g0 / (1.f + __expf(-g0)));
                    float v1 = u1 * (g1 / (1.f + __expf(-g1)));
                    *(float2*)(rowp + nc) = make_float2(v0, v1);
                }
            } else {
                float w = g_w[off + gm] * CBIAS;
                float* rowp = g_dout + (size_t)(off + gm) * H_ + n0;
                #pragma unroll
                for (int ni = 0; ni < 8; ni++) {
                    int nc = wn + ni * 8 + qk * 2;
                    *(float2*)(rowp + nc) = make_float2(acc[mi][ni][half * 2 + 0] * w,
                                                        acc[mi][ni][half * 2 + 1] * w);
                }
            }
        }
    }
}

// ---------------- combine (vectorized float4) ----------------------------------
__global__ void combine_kernel(float4* __restrict__ out) {
    int idx = blockIdx.x * blockDim.x + threadIdx.x;
    if (idx >= T_ * H_ / 4) return;
    int t  = idx >> 9;
    int h4 = idx & 511;
    float4 s = make_float4(0.f, 0.f, 0.f, 0.f);
    #pragma unroll
    for (int k = 0; k < 4; k++) {
        int pos = g_inv[4 * t + k];
        if (pos >= 0) {
            float4 v = *(const float4*)(g_dout + (size_t)pos * H_ + h4 * 4);
            s.x += v.x; s.y += v.y; s.z += v.z; s.w += v.w;
        }
    }
    out[idx] = s;
}

// ---------------- launch --------------------------------------------------------
extern "C" void kernel_launch(void* const* d_in, const int* in_sizes, int n_in,
                              void* d_out, int out_size) {
    const float* hs  = (const float*)d_in[0];
    const float* rw  = (const float*)d_in[1];
    const int*   ri  = (const int*)d_in[2];
    const float* gup = (const float*)d_in[4];
    const float* dn  = (const float*)d_in[5];
    float* out = (float*)d_out;

    cudaFuncSetAttribute((const void*)moe_gemm<2048, true>,
                         cudaFuncAttributeMaxDynamicSharedMemorySize, SMEM_BYTES);
    cudaFuncSetAttribute((const void*)moe_gemm<768, false>,
                         cudaFuncAttributeMaxDynamicSharedMemorySize, SMEM_BYTES);

    route_kernel<<<1, 256>>>(ri, rw);

    // x = m-tile (fastest), y = n-tile, z = expert
    moe_gemm<2048, true><<<dim3(8, 6, E_), 512, SMEM_BYTES>>>(hs, gup);     // gate_up + SwiGLU
    moe_gemm<768, false><<<dim3(8, 8, E_), 512, SMEM_BYTES>>>(nullptr, dn); // down * w

    combine_kernel<<<(T_ * H_ / 4 + 255) / 256, 256>>>((float4*)out);
}

// round 10
// speedup vs baseline: 1.0896x; 1.0896x over previous
#include <cuda_runtime.h>
#include <cstdint>

static constexpr int E_   = 32;
static constexpr int H_   = 2048;
static constexpr int I_   = 768;
static constexpr int T_   = 2048;
static constexpr int MAXA = 8192;

// tf32 truncation-bias correction (validated R2-R9)
static constexpr float CBIAS = 1.000704f;

// ---------------- scratch ----------------------------------------------------
__device__ int   g_counts[E_];
__device__ int   g_offsets[E_];
__device__ int   g_total;
__device__ int   g_tok[MAXA];
__device__ float g_w[MAXA];
__device__ int   g_inv[T_ * 4];
__device__ float g_act[(size_t)MAXA * I_];
__device__ float g_dout[(size_t)MAXA * H_];

__device__ __forceinline__ uint32_t smem_u32(const void* p) {
    uint32_t a;
    asm("{ .reg .u64 t; cvta.to.shared.u64 t, %1; cvt.u32.u64 %0, t; }" : "=r"(a) : "l"(p));
    return a;
}
__device__ __forceinline__ void cpa16(uint32_t dst, const void* src) {
    asm volatile("cp.async.cg.shared.global [%0], [%1], 16;" :: "r"(dst), "l"(src));
}

// ---------------- routing (known-good) ----------------------------------------
__global__ void route_kernel(const int* __restrict__ ridx,
                             const float* __restrict__ rw) {
    __shared__ int s_cnt[E_], s_cur[E_], s_off[E_];
    int tid = threadIdx.x;
    if (tid < E_) { s_cnt[tid] = 0; s_cur[tid] = 0; }
    __syncthreads();
    for (int t = tid; t < T_; t += blockDim.x) {
        int e0 = ridx[4*t], e1 = ridx[4*t+1], e2 = ridx[4*t+2], e3 = ridx[4*t+3];
        if (e0 != e1 && e0 != e2 && e0 != e3) atomicAdd(&s_cnt[e0], 1);
        if (e1 != e2 && e1 != e3)             atomicAdd(&s_cnt[e1], 1);
        if (e2 != e3)                          atomicAdd(&s_cnt[e2], 1);
        atomicAdd(&s_cnt[e3], 1);
    }
    __syncthreads();
    if (tid == 0) {
        int acc = 0;
        for (int e = 0; e < E_; e++) {
            s_off[e] = acc; g_offsets[e] = acc; g_counts[e] = s_cnt[e];
            acc += s_cnt[e];
        }
        g_total = acc;
    }
    __syncthreads();
    for (int t = tid; t < T_; t += blockDim.x) {
        int ee[4]; float ww[4];
        #pragma unroll
        for (int k = 0; k < 4; k++) { ee[k] = ridx[4*t+k]; ww[k] = rw[4*t+k]; }
        #pragma unroll
        for (int k = 0; k < 4; k++) {
            bool keep = true;
            #pragma unroll
            for (int j = k + 1; j < 4; j++) if (ee[j] == ee[k]) keep = false;
            int pos = -1;
            if (keep) {
                pos = s_off[ee[k]] + atomicAdd(&s_cur[ee[k]], 1);
                g_tok[pos] = t; g_w[pos] = ww[k];
            }
            g_inv[4*t + k] = pos;
        }
    }
}

// ---------------- grouped GEMM: 128x256 tile, 8 warps of 64x64, 4-stage -------
// A fragments via ldmatrix.x4; single __syncthreads per chunk.
// FIRST: A = gathered hidden [cnt,2048]; B cols = gate[n0..n0+128)|up[768+n0..);
//        epilogue = SwiGLU -> g_act[.., n0..n0+128)
// else : A = g_act [cnt,768]; B cols = [n0..n0+256); epilogue *w -> g_dout
static constexpr int AS_STRIDE = 36;
static constexpr int AS_BUF    = 128 * AS_STRIDE;   // 4608 u32
static constexpr int BS_STRIDE = 264;
static constexpr int BS_BUF    = 32 * BS_STRIDE;    // 8448 u32
static constexpr int STG       = AS_BUF + BS_BUF;   // 13056 u32 = 52224 B
static constexpr int SMEM_BYTES = 4 * STG * 4;      // 208896 B

template<int KDIM, bool FIRST>
__global__ void __launch_bounds__(256, 1)
moe_gemm(const float* __restrict__ Ain, const float* __restrict__ Bfull) {
    constexpr int NCH    = KDIM / 32;
    constexpr int LDB    = FIRST ? 1536 : 2048;
    constexpr int ROWSPE = FIRST ? 2048 : 768;
    constexpr int NOUT   = FIRST ? 128 : 256;

    extern __shared__ uint32_t sm[];
    const int e   = blockIdx.z;
    const int cnt = g_counts[e];
    const int m0  = blockIdx.x * 128;   // m fastest
    if (m0 >= cnt) return;
    const int off = g_offsets[e];
    const int n0  = blockIdx.y * NOUT;
    const int tid = threadIdx.x;
    const int wid = tid >> 5, lane = tid & 31;
    const uint32_t sbase = smem_u32(sm);

    // ---- A staging: 4 rows/thread, row = p*32 + (tid>>3), seg = tid&7 ----
    const int a_seg = tid & 7;
    const int a_r   = tid >> 3;
    const float* aSrc[4];
    uint32_t aDst[4];
    #pragma unroll
    for (int p = 0; p < 4; p++) {
        int gm = m0 + p * 32 + a_r;
        int rr = (gm < cnt) ? gm : 0;
        aSrc[p] = (FIRST ? Ain + (size_t)g_tok[off + rr] * KDIM
                         : g_act + (size_t)(off + rr) * KDIM) + a_seg * 4;
        aDst[p] = sbase + (uint32_t)((p * 32 + a_r) * AS_STRIDE + a_seg * 4) * 4;
    }
    // ---- B staging: warp = sub-tile nt (32 cols), seg = tid&7, rb = (tid>>3)&3
    const int b_nt  = tid >> 5;
    const int b_seg = tid & 7;
    const int b_rb  = (tid >> 3) & 3;
    const int gcol  = FIRST ? (b_nt < 4 ? n0 + b_nt * 32 : 768 + n0 + (b_nt - 4) * 32)
                            : n0 + b_nt * 32;
    const float* bSrc = Bfull + ((size_t)e * ROWSPE + b_rb) * LDB + gcol + b_seg * 4;
    const uint32_t bDst0 = sbase + (uint32_t)(AS_BUF + b_rb * BS_STRIDE + b_nt * 32 + b_seg * 4) * 4;

    float acc[4][8][4];
    #pragma unroll
    for (int i = 0; i < 4; i++)
        #pragma unroll
        for (int j = 0; j < 8; j++)
            #pragma unroll
            for (int k = 0; k < 4; k++) acc[i][j][k] = 0.f;

    const int wm = (wid >> 2) * 64;                    // 0 / 64
    const int wn = (wid & 3) * (FIRST ? 32 : 64);      // n within acc layout
    const int qr = lane >> 2;
    const int qk = lane & 3;

    // ldmatrix lane address components: grp 0..3 (matrix), rig = row in group
    const int lm_grp = lane >> 3;
    const int lm_rig = lane & 7;
    const uint32_t lm_row  = (uint32_t)(wm + (lm_grp & 1) * 8 + lm_rig);
    const uint32_t lm_base = (lm_row * AS_STRIDE + (uint32_t)(lm_grp >> 1) * 4) * 4;

    auto load_chunk = [&](int c) {
        const uint32_t so = (uint32_t)(c & 3) * (STG * 4);
        const size_t akc = (size_t)c * 32;
        #pragma unroll
        for (int p = 0; p < 4; p++) cpa16(aDst[p] + so, aSrc[p] + akc);
        const float* bp = bSrc + (size_t)c * 32 * LDB;
        #pragma unroll
        for (int p = 0; p < 8; p++)
            cpa16(bDst0 + so + (uint32_t)(p * 4 * BS_STRIDE) * 4, bp + (size_t)p * 4 * LDB);
        asm volatile("cp.async.commit_group;" ::: "memory");
    };

    load_chunk(0); load_chunk(1); load_chunk(2);

    for (int c = 0; c < NCH; c++) {
        int rem = NCH - 1 - c;
        if (rem >= 2)      asm volatile("cp.async.wait_group 2;" ::: "memory");
        else if (rem == 1) asm volatile("cp.async.wait_group 1;" ::: "memory");
        else               asm volatile("cp.async.wait_group 0;" ::: "memory");
        __syncthreads();   // single barrier per chunk: also protects load(c+3)'s
                           // overwrite of buffer (c-1)&3 (compute(c-1) done by all)
        if (c + 3 < NCH) load_chunk(c + 3);

        const uint32_t stg_off = (uint32_t)(c & 3) * (STG * 4);
        const uint32_t a_lm = sbase + stg_off + lm_base;
        const uint32_t* Bs = sm + (c & 3) * STG + AS_BUF;
        #pragma unroll
        for (int kk = 0; kk < 32; kk += 8) {
            uint32_t af[4][4], bf[8][2];
            #pragma unroll
            for (int mi = 0; mi < 4; mi++) {
                uint32_t addr = a_lm + (uint32_t)(mi * 16 * AS_STRIDE + kk) * 4;
                asm volatile(
                    "ldmatrix.sync.aligned.m8n8.x4.shared.b16 {%0,%1,%2,%3}, [%4];"
                    : "=r"(af[mi][0]), "=r"(af[mi][1]),
                      "=r"(af[mi][2]), "=r"(af[mi][3])
                    : "r"(addr));
            }
            #pragma unroll
            for (int ni = 0; ni < 8; ni++) {
                int nc = FIRST ? (ni < 4 ? wn + ni * 8 + qr : 128 + wn + (ni - 4) * 8 + qr)
                               : wn + ni * 8 + qr;
                bf[ni][0] = Bs[(kk + qk) * BS_STRIDE + nc];
                bf[ni][1] = Bs[(kk + qk + 4) * BS_STRIDE + nc];
            }
            #pragma unroll
            for (int mi = 0; mi < 4; mi++)
                #pragma unroll
                for (int ni = 0; ni < 8; ni++)
                    asm volatile(
                        "mma.sync.aligned.m16n8k8.row.col.f32.tf32.tf32.f32 "
                        "{%0,%1,%2,%3}, {%4,%5,%6,%7}, {%8,%9}, {%0,%1,%2,%3};"
                        : "+f"(acc[mi][ni][0]), "+f"(acc[mi][ni][1]),
                          "+f"(acc[mi][ni][2]), "+f"(acc[mi][ni][3])
                        : "r"(af[mi][0]), "r"(af[mi][1]),
                          "r"(af[mi][2]), "r"(af[mi][3]),
                          "r"(bf[ni][0]), "r"(bf[ni][1]));
        }
    }
    __syncthreads();

    // ---- epilogue ----
    #pragma unroll
    for (int mi = 0; mi < 4; mi++) {
        #pragma unroll
        for (int half = 0; half < 2; half++) {
            int r  = wm + mi * 16 + qr + half * 8;
            int gm = m0 + r;
            if (gm >= cnt) continue;
            if (FIRST) {
                float* rowp = g_act + (size_t)(off + gm) * I_ + n0;
                #pragma unroll
                for (int ni = 0; ni < 4; ni++) {
                    int nc = wn + ni * 8 + qk * 2;
                    float g0 = acc[mi][ni][half * 2 + 0] * CBIAS;
                    float g1 = acc[mi][ni][half * 2 + 1] * CBIAS;
                    float u0 = acc[mi][ni + 4][half * 2 + 0] * CBIAS;
                    float u1 = acc[mi][ni + 4][half * 2 + 1] * CBIAS;
                    float v0 = u0 * (g0 / (1.f + __expf(-g0)));
                    float v1 = u1 * (g1 / (1.f + __expf(-g1)));
                    *(float2*)(rowp + nc) = make_float2(v0, v1);
                }
            } else {
                float w = g_w[off + gm] * CBIAS;
                float* rowp = g_dout + (size_t)(off + gm) * H_ + n0;
                #pragma unroll
                for (int ni = 0; ni < 8; ni++) {
                    int nc = wn + ni * 8 + qk * 2;
                    *(float2*)(rowp + nc) = make_float2(acc[mi][ni][half * 2 + 0] * w,
                                                        acc[mi][ni][half * 2 + 1] * w);
                }
            }
        }
    }
}

// ---------------- combine (vectorized float4) ----------------------------------
__global__ void combine_kernel(float4* __restrict__ out) {
    int idx = blockIdx.x * blockDim.x + threadIdx.x;
    if (idx >= T_ * H_ / 4) return;
    int t  = idx >> 9;
    int h4 = idx & 511;
    float4 s = make_float4(0.f, 0.f, 0.f, 0.f);
    #pragma unroll
    for (int k = 0; k < 4; k++) {
        int pos = g_inv[4 * t + k];
        if (pos >= 0) {
            float4 v = *(const float4*)(g_dout + (size_t)pos * H_ + h4 * 4);
            s.x += v.x; s.y += v.y; s.z += v.z; s.w += v.w;
        }
    }
    out[idx] = s;
}

// ---------------- launch --------------------------------------------------------
extern "C" void kernel_launch(void* const* d_in, const int* in_sizes, int n_in,
                              void* d_out, int out_size) {
    const float* hs  = (const float*)d_in[0];
    const float* rw  = (const float*)d_in[1];
    const int*   ri  = (const int*)d_in[2];
    const float* gup = (const float*)d_in[4];
    const float* dn  = (const float*)d_in[5];
    float* out = (float*)d_out;

    cudaFuncSetAttribute((const void*)moe_gemm<2048, true>,
                         cudaFuncAttributeMaxDynamicSharedMemorySize, SMEM_BYTES);
    cudaFuncSetAttribute((const void*)moe_gemm<768, false>,
                         cudaFuncAttributeMaxDynamicSharedMemorySize, SMEM_BYTES);

    route_kernel<<<1, 256>>>(ri, rw);

    // x = m-tile (fastest), y = n-tile, z = expert
    moe_gemm<2048, true><<<dim3(8, 6, E_), 256, SMEM_BYTES>>>(hs, gup);     // gate_up + SwiGLU
    moe_gemm<768, false><<<dim3(8, 8, E_), 256, SMEM_BYTES>>>(nullptr, dn); // down * w

    combine_kernel<<<(T_ * H_ / 4 + 255) / 256, 256>>>((float4*)out);
}

// round 11
// speedup vs baseline: 1.2540x; 1.1509x over previous
#include <cuda_runtime.h>
#include <cuda_fp16.h>
#include <cstdint>

static constexpr int E_   = 32;
static constexpr int H_   = 2048;
static constexpr int I_   = 768;
static constexpr int T_   = 2048;
static constexpr int MAXA = 8192;

// ---------------- scratch ----------------------------------------------------
__device__ int   g_counts[E_];
__device__ int   g_offsets[E_];
__device__ int   g_total;
__device__ int   g_tok[MAXA];
__device__ float g_w[MAXA];
__device__ int   g_inv[T_ * 4];
__device__ __align__(16) __half g_hs16[(size_t)T_ * H_];          //  8.4 MB
__device__ __align__(16) __half g_gup16[(size_t)E_ * H_ * 1536];  //  201 MB
__device__ __align__(16) __half g_dn16[(size_t)E_ * I_ * H_];     //  100 MB
__device__ __align__(16) __half g_act16[(size_t)MAXA * I_];       //  12.6 MB
__device__ float g_dout[(size_t)MAXA * H_];

__device__ __forceinline__ uint32_t smem_u32(const void* p) {
    uint32_t a;
    asm("{ .reg .u64 t; cvta.to.shared.u64 t, %1; cvt.u32.u64 %0, t; }" : "=r"(a) : "l"(p));
    return a;
}
__device__ __forceinline__ void cpa16(uint32_t dst, const void* src) {
    asm volatile("cp.async.cg.shared.global [%0], [%1], 16;" :: "r"(dst), "l"(src));
}

// ---------------- fp32 -> fp16 streaming convert -------------------------------
__global__ void cvt_kernel(const float4* __restrict__ in, __half2* __restrict__ out, int n4) {
    for (int i = blockIdx.x * blockDim.x + threadIdx.x; i < n4;
         i += gridDim.x * blockDim.x) {
        float4 v = in[i];
        out[2 * i]     = __floats2half2_rn(v.x, v.y);
        out[2 * i + 1] = __floats2half2_rn(v.z, v.w);
    }
}

// ---------------- routing (known-good) ----------------------------------------
__global__ void route_kernel(const int* __restrict__ ridx,
                             const float* __restrict__ rw) {
    __shared__ int s_cnt[E_], s_cur[E_], s_off[E_];
    int tid = threadIdx.x;
    if (tid < E_) { s_cnt[tid] = 0; s_cur[tid] = 0; }
    __syncthreads();
    for (int t = tid; t < T_; t += blockDim.x) {
        int e0 = ridx[4*t], e1 = ridx[4*t+1], e2 = ridx[4*t+2], e3 = ridx[4*t+3];
        if (e0 != e1 && e0 != e2 && e0 != e3) atomicAdd(&s_cnt[e0], 1);
        if (e1 != e2 && e1 != e3)             atomicAdd(&s_cnt[e1], 1);
        if (e2 != e3)                          atomicAdd(&s_cnt[e2], 1);
        atomicAdd(&s_cnt[e3], 1);
    }
    __syncthreads();
    if (tid == 0) {
        int acc = 0;
        for (int e = 0; e < E_; e++) {
            s_off[e] = acc; g_offsets[e] = acc; g_counts[e] = s_cnt[e];
            acc += s_cnt[e];
        }
        g_total = acc;
    }
    __syncthreads();
    for (int t = tid; t < T_; t += blockDim.x) {
        int ee[4]; float ww[4];
        #pragma unroll
        for (int k = 0; k < 4; k++) { ee[k] = ridx[4*t+k]; ww[k] = rw[4*t+k]; }
        #pragma unroll
        for (int k = 0; k < 4; k++) {
            bool keep = true;
            #pragma unroll
            for (int j = k + 1; j < 4; j++) if (ee[j] == ee[k]) keep = false;
            int pos = -1;
            if (keep) {
                pos = s_off[ee[k]] + atomicAdd(&s_cur[ee[k]], 1);
                g_tok[pos] = t; g_w[pos] = ww[k];
            }
            g_inv[4*t + k] = pos;
        }
    }
}

// ---------------- fp16 grouped GEMM: 128x256 tile, 8 warps 64x64, k-chunk 64 ---
// Byte layout per stage: A [128 rows][144 B] then B [64 rows][528 B].
static constexpr int A_PITCH = 144;                  // 72 fp16
static constexpr int B_PITCH = 528;                  // 264 fp16
static constexpr int A_BYTES = 128 * A_PITCH;        // 18432
static constexpr int B_BYTES = 64 * B_PITCH;         // 33792
static constexpr int STG_B   = A_BYTES + B_BYTES;    // 52224
static constexpr int SMEM_BYTES = 4 * STG_B;         // 208896

template<int KDIM, bool FIRST>
__global__ void __launch_bounds__(256, 1)
moe_gemm(const __half* __restrict__ Ain, const __half* __restrict__ B16) {
    constexpr int NCH    = KDIM / 64;
    constexpr int LDB    = FIRST ? 1536 : 2048;
    constexpr int ROWSPE = FIRST ? 2048 : 768;
    constexpr int NOUT   = FIRST ? 128 : 256;

    extern __shared__ uint8_t smraw[];
    const int e   = blockIdx.z;
    const int cnt = g_counts[e];
    const int m0  = blockIdx.x * 128;
    if (m0 >= cnt) return;
    const int off = g_offsets[e];
    const int n0  = blockIdx.y * NOUT;
    const int tid = threadIdx.x;
    const int wid = tid >> 5, lane = tid & 31;
    const uint32_t sbase = smem_u32(smraw);

    // ---- A staging: 4 segs/thread; row = p*32 + (tid>>3), seg = tid&7 (16B) --
    const int a_seg = tid & 7;
    const int a_r   = tid >> 3;
    const __half* aSrc[4];
    uint32_t aDst[4];
    #pragma unroll
    for (int p = 0; p < 4; p++) {
        int gm = m0 + p * 32 + a_r;
        int rr = (gm < cnt) ? gm : 0;
        aSrc[p] = (FIRST ? Ain + (size_t)g_tok[off + rr] * KDIM
                         : g_act16 + (size_t)(off + rr) * KDIM) + a_seg * 8;
        aDst[p] = sbase + (uint32_t)((p * 32 + a_r) * A_PITCH + a_seg * 16);
    }
    // ---- B staging: 8 segs/thread; row = (tid>>5)+8p (0..63), seg = tid&31 ---
    const int b_s = tid & 31;
    const int b_r = tid >> 5;
    const int gcol = FIRST ? (b_s < 16 ? n0 + b_s * 8 : 768 + n0 + (b_s - 16) * 8)
                           : n0 + b_s * 8;
    const __half* bSrc0 = B16 + ((size_t)e * ROWSPE + b_r) * LDB + gcol;
    const uint32_t bDst0 = sbase + (uint32_t)(A_BYTES + b_r * B_PITCH + b_s * 16);

    float acc[4][8][4];
    #pragma unroll
    for (int i = 0; i < 4; i++)
        #pragma unroll
        for (int j = 0; j < 8; j++)
            #pragma unroll
            for (int k = 0; k < 4; k++) acc[i][j][k] = 0.f;

    const int wm = (wid >> 2) * 64;                    // 0 / 64
    const int wn = (wid & 3) * (FIRST ? 32 : 64);
    const int qr = lane >> 2;
    const int qk = lane & 3;

    // ldmatrix address bases (per-lane):
    // A (x4 non-trans): row = wm + mi*16 + (lane&15); byte col = kk*2 + (lane>>4)*16
    const uint32_t a_lm_row = (uint32_t)(wm + (lane & 15));
    const uint32_t a_lm_off = a_lm_row * A_PITCH + (uint32_t)((lane >> 4) * 16);
    // B (x4 trans): k-row = kk + (lane&7) + ((lane>>3)&1)*8; n-col = nb + (lane>>4)*8
    const uint32_t b_lm_krow = (uint32_t)((lane & 7) + ((lane >> 3) & 1) * 8);
    const uint32_t b_lm_noff = (uint32_t)((lane >> 4) * 8 * 2);

    auto load_chunk = [&](int c) {
        const uint32_t so = (uint32_t)(c & 3) * STG_B;
        const size_t akc = (size_t)c * 64;
        #pragma unroll
        for (int p = 0; p < 4; p++) cpa16(aDst[p] + so, aSrc[p] + akc);
        const __half* bp = bSrc0 + (size_t)c * 64 * LDB;
        #pragma unroll
        for (int p = 0; p < 8; p++)
            cpa16(bDst0 + so + (uint32_t)(p * 8 * B_PITCH), bp + (size_t)p * 8 * LDB);
        asm volatile("cp.async.commit_group;" ::: "memory");
    };

    load_chunk(0); load_chunk(1); load_chunk(2);

    for (int c = 0; c < NCH; c++) {
        int rem = NCH - 1 - c;
        if (rem >= 2)      asm volatile("cp.async.wait_group 2;" ::: "memory");
        else if (rem == 1) asm volatile("cp.async.wait_group 1;" ::: "memory");
        else               asm volatile("cp.async.wait_group 0;" ::: "memory");
        __syncthreads();   // also protects load(c+3) overwrite of buffer (c-1)&3
        if (c + 3 < NCH) load_chunk(c + 3);

        const uint32_t sA = sbase + (uint32_t)(c & 3) * STG_B;
        const uint32_t sB = sA + A_BYTES;
        #pragma unroll
        for (int kk = 0; kk < 64; kk += 16) {
            uint32_t af[4][4], bf[8][2];
            #pragma unroll
            for (int mi = 0; mi < 4; mi++) {
                uint32_t addr = sA + a_lm_off + (uint32_t)(mi * 16 * A_PITCH + kk * 2);
                asm volatile(
                    "ldmatrix.sync.aligned.m8n8.x4.shared.b16 {%0,%1,%2,%3}, [%4];"
                    : "=r"(af[mi][0]), "=r"(af[mi][1]),
                      "=r"(af[mi][2]), "=r"(af[mi][3])
                    : "r"(addr));
            }
            #pragma unroll
            for (int nip = 0; nip < 4; nip++) {       // ni pair (2*nip, 2*nip+1)
                int ni = 2 * nip;
                int nb = FIRST ? (ni < 4 ? wn + ni * 8 : 128 + wn + (ni - 4) * 8)
                               : wn + ni * 8;
                uint32_t addr = sB + (kk + b_lm_krow) * B_PITCH
                                   + (uint32_t)(nb * 2) + b_lm_noff;
                asm volatile(
                    "ldmatrix.sync.aligned.m8n8.x4.trans.shared.b16 {%0,%1,%2,%3}, [%4];"
                    : "=r"(bf[ni][0]), "=r"(bf[ni][1]),
                      "=r"(bf[ni + 1][0]), "=r"(bf[ni + 1][1])
                    : "r"(addr));
            }
            #pragma unroll
            for (int mi = 0; mi < 4; mi++)
                #pragma unroll
                for (int ni = 0; ni < 8; ni++)
                    asm volatile(
                        "mma.sync.aligned.m16n8k16.row.col.f32.f16.f16.f32 "
                        "{%0,%1,%2,%3}, {%4,%5,%6,%7}, {%8,%9}, {%0,%1,%2,%3};"
                        : "+f"(acc[mi][ni][0]), "+f"(acc[mi][ni][1]),
                          "+f"(acc[mi][ni][2]), "+f"(acc[mi][ni][3])
                        : "r"(af[mi][0]), "r"(af[mi][1]),
                          "r"(af[mi][2]), "r"(af[mi][3]),
                          "r"(bf[ni][0]), "r"(bf[ni][1]));
        }
    }
    __syncthreads();

    // ---- epilogue ----
    #pragma unroll
    for (int mi = 0; mi < 4; mi++) {
        #pragma unroll
        for (int half = 0; half < 2; half++) {
            int r  = wm + mi * 16 + qr + half * 8;
            int gm = m0 + r;
            if (gm >= cnt) continue;
            if (FIRST) {
                __half* rowp = g_act16 + (size_t)(off + gm) * I_ + n0;
                #pragma unroll
                for (int ni = 0; ni < 4; ni++) {
                    int nc = wn + ni * 8 + qk * 2;
                    float g0 = acc[mi][ni][half * 2 + 0];
                    float g1 = acc[mi][ni][half * 2 + 1];
                    float u0 = acc[mi][ni + 4][half * 2 + 0];
                    float u1 = acc[mi][ni + 4][half * 2 + 1];
                    float v0 = u0 * (g0 / (1.f + __expf(-g0)));
                    float v1 = u1 * (g1 / (1.f + __expf(-g1)));
                    *(__half2*)(rowp + nc) = __floats2half2_rn(v0, v1);
                }
            } else {
                float w = g_w[off + gm];
                float* rowp = g_dout + (size_t)(off + gm) * H_ + n0;
                #pragma unroll
                for (int ni = 0; ni < 8; ni++) {
                    int nc = wn + ni * 8 + qk * 2;
                    *(float2*)(rowp + nc) = make_float2(acc[mi][ni][half * 2 + 0] * w,
                                                        acc[mi][ni][half * 2 + 1] * w);
                }
            }
        }
    }
}

// ---------------- combine (vectorized float4) ----------------------------------
__global__ void combine_kernel(float4* __restrict__ out) {
    int idx = blockIdx.x * blockDim.x + threadIdx.x;
    if (idx >= T_ * H_ / 4) return;
    int t  = idx >> 9;
    int h4 = idx & 511;
    float4 s = make_float4(0.f, 0.f, 0.f, 0.f);
    #pragma unroll
    for (int k = 0; k < 4; k++) {
        int pos = g_inv[4 * t + k];
        if (pos >= 0) {
            float4 v = *(const float4*)(g_dout + (size_t)pos * H_ + h4 * 4);
            s.x += v.x; s.y += v.y; s.z += v.z; s.w += v.w;
        }
    }
    out[idx] = s;
}

// ---------------- launch --------------------------------------------------------
extern "C" void kernel_launch(void* const* d_in, const int* in_sizes, int n_in,
                              void* d_out, int out_size) {
    const float* hs  = (const float*)d_in[0];
    const float* rw  = (const float*)d_in[1];
    const int*   ri  = (const int*)d_in[2];
    const float* gup = (const float*)d_in[4];
    const float* dn  = (const float*)d_in[5];
    float* out = (float*)d_out;

    cudaFuncSetAttribute((const void*)moe_gemm<2048, true>,
                         cudaFuncAttributeMaxDynamicSharedMemorySize, SMEM_BYTES);
    cudaFuncSetAttribute((const void*)moe_gemm<768, false>,
                         cudaFuncAttributeMaxDynamicSharedMemorySize, SMEM_BYTES);

    route_kernel<<<1, 256>>>(ri, rw);

    __half2* gup16; cudaGetSymbolAddress((void**)&gup16, g_gup16);
    __half2* dn16;  cudaGetSymbolAddress((void**)&dn16,  g_dn16);
    __half2* hs16;  cudaGetSymbolAddress((void**)&hs16,  g_hs16);

    cvt_kernel<<<4096, 256>>>((const float4*)gup, gup16, E_ * H_ * 1536 / 4);
    cvt_kernel<<<4096, 256>>>((const float4*)dn,  dn16,  E_ * I_ * H_ / 4);
    cvt_kernel<<<1024, 256>>>((const float4*)hs,  hs16,  T_ * H_ / 4);

    const __half* hs16c; cudaGetSymbolAddress((void**)&hs16c, g_hs16);
    const __half* gupc;  cudaGetSymbolAddress((void**)&gupc,  g_gup16);
    const __half* dnc;   cudaGetSymbolAddress((void**)&dnc,   g_dn16);

    // x = m-tile (fastest), y = n-tile, z = expert
    moe_gemm<2048, true><<<dim3(8, 6, E_), 256, SMEM_BYTES>>>(hs16c, gupc);
    moe_gemm<768, false><<<dim3(8, 8, E_), 256, SMEM_BYTES>>>(nullptr, dnc);

    combine_kernel<<<(T_ * H_ / 4 + 255) / 256, 256>>>((float4*)out);
}

// round 12
// speedup vs baseline: 1.2682x; 1.0114x over previous
#include <cuda_runtime.h>
#include <cuda_fp16.h>
#include <cstdint>

static constexpr int E_   = 32;
static constexpr int H_   = 2048;
static constexpr int I_   = 768;
static constexpr int T_   = 2048;
static constexpr int MAXA = 8192;

// ---------------- scratch ----------------------------------------------------
__device__ int   g_counts[E_];
__device__ int   g_offsets[E_];
__device__ int   g_total;
__device__ int   g_tok[MAXA];
__device__ float g_w[MAXA];
__device__ int   g_inv[T_ * 4];
__device__ __align__(16) __half g_hs16[(size_t)T_ * H_];
__device__ __align__(16) __half g_gup16[(size_t)E_ * H_ * 1536];
__device__ __align__(16) __half g_dn16[(size_t)E_ * I_ * H_];
__device__ __align__(16) __half g_act16[(size_t)MAXA * I_];
__device__ __align__(16) __half g_dout16[(size_t)MAXA * H_];

__device__ __forceinline__ uint32_t smem_u32(const void* p) {
    uint32_t a;
    asm("{ .reg .u64 t; cvta.to.shared.u64 t, %1; cvt.u32.u64 %0, t; }" : "=r"(a) : "l"(p));
    return a;
}
__device__ __forceinline__ void cpa16(uint32_t dst, const void* src) {
    asm volatile("cp.async.cg.shared.global [%0], [%1], 16;" :: "r"(dst), "l"(src));
}

// ---------------- fp32 -> fp16 streaming convert -------------------------------
__global__ void cvt_kernel(const float4* __restrict__ in, __half2* __restrict__ out, int n4) {
    for (int i = blockIdx.x * blockDim.x + threadIdx.x; i < n4;
         i += gridDim.x * blockDim.x) {
        float4 v = in[i];
        out[2 * i]     = __floats2half2_rn(v.x, v.y);
        out[2 * i + 1] = __floats2half2_rn(v.z, v.w);
    }
}

// ---------------- routing (known-good) ----------------------------------------
__global__ void route_kernel(const int* __restrict__ ridx,
                             const float* __restrict__ rw) {
    __shared__ int s_cnt[E_], s_cur[E_], s_off[E_];
    int tid = threadIdx.x;
    if (tid < E_) { s_cnt[tid] = 0; s_cur[tid] = 0; }
    __syncthreads();
    for (int t = tid; t < T_; t += blockDim.x) {
        int e0 = ridx[4*t], e1 = ridx[4*t+1], e2 = ridx[4*t+2], e3 = ridx[4*t+3];
        if (e0 != e1 && e0 != e2 && e0 != e3) atomicAdd(&s_cnt[e0], 1);
        if (e1 != e2 && e1 != e3)             atomicAdd(&s_cnt[e1], 1);
        if (e2 != e3)                          atomicAdd(&s_cnt[e2], 1);
        atomicAdd(&s_cnt[e3], 1);
    }
    __syncthreads();
    if (tid == 0) {
        int acc = 0;
        for (int e = 0; e < E_; e++) {
            s_off[e] = acc; g_offsets[e] = acc; g_counts[e] = s_cnt[e];
            acc += s_cnt[e];
        }
        g_total = acc;
    }
    __syncthreads();
    for (int t = tid; t < T_; t += blockDim.x) {
        int ee[4]; float ww[4];
        #pragma unroll
        for (int k = 0; k < 4; k++) { ee[k] = ridx[4*t+k]; ww[k] = rw[4*t+k]; }
        #pragma unroll
        for (int k = 0; k < 4; k++) {
            bool keep = true;
            #pragma unroll
            for (int j = k + 1; j < 4; j++) if (ee[j] == ee[k]) keep = false;
            int pos = -1;
            if (keep) {
                pos = s_off[ee[k]] + atomicAdd(&s_cur[ee[k]], 1);
                g_tok[pos] = t; g_w[pos] = ww[k];
            }
            g_inv[4*t + k] = pos;
        }
    }
}

// ---------------- fp16 grouped GEMM: 128x256 tile, 8 warps 64x64, k-chunk 64 ---
static constexpr int A_PITCH = 144;
static constexpr int B_PITCH = 528;
static constexpr int A_BYTES = 128 * A_PITCH;        // 18432
static constexpr int B_BYTES = 64 * B_PITCH;         // 33792
static constexpr int STG_B   = A_BYTES + B_BYTES;    // 52224
static constexpr int SMEM_BYTES = 4 * STG_B;         // 208896

template<int KDIM, bool FIRST>
__global__ void __launch_bounds__(256, 1)
moe_gemm(const __half* __restrict__ Ain, const __half* __restrict__ B16) {
    constexpr int NCH    = KDIM / 64;
    constexpr int LDB    = FIRST ? 1536 : 2048;
    constexpr int ROWSPE = FIRST ? 2048 : 768;
    constexpr int NOUT   = FIRST ? 128 : 256;

    extern __shared__ uint8_t smraw[];
    const int e   = blockIdx.z;
    const int cnt = g_counts[e];
    const int m0  = blockIdx.x * 128;
    if (m0 >= cnt) return;
    const int off = g_offsets[e];
    const int n0  = blockIdx.y * NOUT;
    const int tid = threadIdx.x;
    const int wid = tid >> 5, lane = tid & 31;
    const uint32_t sbase = smem_u32(smraw);

    const int a_seg = tid & 7;
    const int a_r   = tid >> 3;
    const __half* aSrc[4];
    uint32_t aDst[4];
    #pragma unroll
    for (int p = 0; p < 4; p++) {
        int gm = m0 + p * 32 + a_r;
        int rr = (gm < cnt) ? gm : 0;
        aSrc[p] = (FIRST ? Ain + (size_t)g_tok[off + rr] * KDIM
                         : g_act16 + (size_t)(off + rr) * KDIM) + a_seg * 8;
        aDst[p] = sbase + (uint32_t)((p * 32 + a_r) * A_PITCH + a_seg * 16);
    }
    const int b_s = tid & 31;
    const int b_r = tid >> 5;
    const int gcol = FIRST ? (b_s < 16 ? n0 + b_s * 8 : 768 + n0 + (b_s - 16) * 8)
                           : n0 + b_s * 8;
    const __half* bSrc0 = B16 + ((size_t)e * ROWSPE + b_r) * LDB + gcol;
    const uint32_t bDst0 = sbase + (uint32_t)(A_BYTES + b_r * B_PITCH + b_s * 16);

    float acc[4][8][4];
    #pragma unroll
    for (int i = 0; i < 4; i++)
        #pragma unroll
        for (int j = 0; j < 8; j++)
            #pragma unroll
            for (int k = 0; k < 4; k++) acc[i][j][k] = 0.f;

    const int wm = (wid >> 2) * 64;
    const int wn = (wid & 3) * (FIRST ? 32 : 64);
    const int qr = lane >> 2;
    const int qk = lane & 3;

    const uint32_t a_lm_row = (uint32_t)(wm + (lane & 15));
    const uint32_t a_lm_off = a_lm_row * A_PITCH + (uint32_t)((lane >> 4) * 16);
    const uint32_t b_lm_krow = (uint32_t)((lane & 7) + ((lane >> 3) & 1) * 8);
    const uint32_t b_lm_noff = (uint32_t)((lane >> 4) * 8 * 2);

    auto load_chunk = [&](int c) {
        const uint32_t so = (uint32_t)(c & 3) * STG_B;
        const size_t akc = (size_t)c * 64;
        #pragma unroll
        for (int p = 0; p < 4; p++) cpa16(aDst[p] + so, aSrc[p] + akc);
        const __half* bp = bSrc0 + (size_t)c * 64 * LDB;
        #pragma unroll
        for (int p = 0; p < 8; p++)
            cpa16(bDst0 + so + (uint32_t)(p * 8 * B_PITCH), bp + (size_t)p * 8 * LDB);
        asm volatile("cp.async.commit_group;" ::: "memory");
    };

    load_chunk(0); load_chunk(1); load_chunk(2);

    for (int c = 0; c < NCH; c++) {
        int rem = NCH - 1 - c;
        if (rem >= 2)      asm volatile("cp.async.wait_group 2;" ::: "memory");
        else if (rem == 1) asm volatile("cp.async.wait_group 1;" ::: "memory");
        else               asm volatile("cp.async.wait_group 0;" ::: "memory");
        __syncthreads();
        if (c + 3 < NCH) load_chunk(c + 3);

        const uint32_t sA = sbase + (uint32_t)(c & 3) * STG_B;
        const uint32_t sB = sA + A_BYTES;
        #pragma unroll
        for (int kk = 0; kk < 64; kk += 16) {
            uint32_t af[4][4], bf[8][2];
            #pragma unroll
            for (int mi = 0; mi < 4; mi++) {
                uint32_t addr = sA + a_lm_off + (uint32_t)(mi * 16 * A_PITCH + kk * 2);
                asm volatile(
                    "ldmatrix.sync.aligned.m8n8.x4.shared.b16 {%0,%1,%2,%3}, [%4];"
                    : "=r"(af[mi][0]), "=r"(af[mi][1]),
                      "=r"(af[mi][2]), "=r"(af[mi][3])
                    : "r"(addr));
            }
            #pragma unroll
            for (int nip = 0; nip < 4; nip++) {
                int ni = 2 * nip;
                int nb = FIRST ? (ni < 4 ? wn + ni * 8 : 128 + wn + (ni - 4) * 8)
                               : wn + ni * 8;
                uint32_t addr = sB + (kk + b_lm_krow) * B_PITCH
                                   + (uint32_t)(nb * 2) + b_lm_noff;
                asm volatile(
                    "ldmatrix.sync.aligned.m8n8.x4.trans.shared.b16 {%0,%1,%2,%3}, [%4];"
                    : "=r"(bf[ni][0]), "=r"(bf[ni][1]),
                      "=r"(bf[ni + 1][0]), "=r"(bf[ni + 1][1])
                    : "r"(addr));
            }
            #pragma unroll
            for (int mi = 0; mi < 4; mi++)
                #pragma unroll
                for (int ni = 0; ni < 8; ni++)
                    asm volatile(
                        "mma.sync.aligned.m16n8k16.row.col.f32.f16.f16.f32 "
                        "{%0,%1,%2,%3}, {%4,%5,%6,%7}, {%8,%9}, {%0,%1,%2,%3};"
                        : "+f"(acc[mi][ni][0]), "+f"(acc[mi][ni][1]),
                          "+f"(acc[mi][ni][2]), "+f"(acc[mi][ni][3])
                        : "r"(af[mi][0]), "r"(af[mi][1]),
                          "r"(af[mi][2]), "r"(af[mi][3]),
                          "r"(bf[ni][0]), "r"(bf[ni][1]));
        }
    }
    __syncthreads();

    // ---- epilogue ----
    #pragma unroll
    for (int mi = 0; mi < 4; mi++) {
        #pragma unroll
        for (int half = 0; half < 2; half++) {
            int r  = wm + mi * 16 + qr + half * 8;
            int gm = m0 + r;
            if (gm >= cnt) continue;
            if (FIRST) {
                __half* rowp = g_act16 + (size_t)(off + gm) * I_ + n0;
                #pragma unroll
                for (int ni = 0; ni < 4; ni++) {
                    int nc = wn + ni * 8 + qk * 2;
                    float g0 = acc[mi][ni][half * 2 + 0];
                    float g1 = acc[mi][ni][half * 2 + 1];
                    float u0 = acc[mi][ni + 4][half * 2 + 0];
                    float u1 = acc[mi][ni + 4][half * 2 + 1];
                    float v0 = u0 * (g0 / (1.f + __expf(-g0)));
                    float v1 = u1 * (g1 / (1.f + __expf(-g1)));
                    *(__half2*)(rowp + nc) = __floats2half2_rn(v0, v1);
                }
            } else {
                float w = g_w[off + gm];
                __half* rowp = g_dout16 + (size_t)(off + gm) * H_ + n0;
                #pragma unroll
                for (int ni = 0; ni < 8; ni++) {
                    int nc = wn + ni * 8 + qk * 2;
                    *(__half2*)(rowp + nc) =
                        __floats2half2_rn(acc[mi][ni][half * 2 + 0] * w,
                                          acc[mi][ni][half * 2 + 1] * w);
                }
            }
        }
    }
}

// ---------------- combine: fp16 dout -> fp32 out --------------------------------
__global__ void combine_kernel(float4* __restrict__ out) {
    int idx = blockIdx.x * blockDim.x + threadIdx.x;
    if (idx >= T_ * H_ / 4) return;
    int t  = idx >> 9;
    int h4 = idx & 511;
    float4 s = make_float4(0.f, 0.f, 0.f, 0.f);
    #pragma unroll
    for (int k = 0; k < 4; k++) {
        int pos = g_inv[4 * t + k];
        if (pos >= 0) {
            const __half2* p = (const __half2*)(g_dout16 + (size_t)pos * H_ + h4 * 4);
            float2 a = __half22float2(p[0]);
            float2 b = __half22float2(p[1]);
            s.x += a.x; s.y += a.y; s.z += b.x; s.w += b.y;
        }
    }
    out[idx] = s;
}

// ---------------- launch --------------------------------------------------------
extern "C" void kernel_launch(void* const* d_in, const int* in_sizes, int n_in,
                              void* d_out, int out_size) {
    const float* hs  = (const float*)d_in[0];
    const float* rw  = (const float*)d_in[1];
    const int*   ri  = (const int*)d_in[2];
    const float* gup = (const float*)d_in[4];
    const float* dn  = (const float*)d_in[5];
    float* out = (float*)d_out;

    // one-time host resources (created outside capture on the correctness call)
    static cudaStream_t s2 = nullptr;
    static cudaEvent_t ev1 = nullptr, ev2 = nullptr;
    if (!s2) {
        cudaStreamCreateWithFlags(&s2, cudaStreamNonBlocking);
        cudaEventCreateWithFlags(&ev1, cudaEventDisableTiming);
        cudaEventCreateWithFlags(&ev2, cudaEventDisableTiming);
    }

    cudaFuncSetAttribute((const void*)moe_gemm<2048, true>,
                         cudaFuncAttributeMaxDynamicSharedMemorySize, SMEM_BYTES);
    cudaFuncSetAttribute((const void*)moe_gemm<768, false>,
                         cudaFuncAttributeMaxDynamicSharedMemorySize, SMEM_BYTES);

    __half2* gup16; cudaGetSymbolAddress((void**)&gup16, g_gup16);
    __half2* dn16;  cudaGetSymbolAddress((void**)&dn16,  g_dn16);
    __half2* hs16;  cudaGetSymbolAddress((void**)&hs16,  g_hs16);
    const __half* hs16c = (const __half*)hs16;
    const __half* gupc  = (const __half*)gup16;
    const __half* dnc   = (const __half*)dn16;

    route_kernel<<<1, 256>>>(ri, rw);
    cvt_kernel<<<1024, 256>>>((const float4*)hs,  hs16,  T_ * H_ / 4);
    cvt_kernel<<<4096, 256>>>((const float4*)gup, gup16, E_ * H_ * 1536 / 4);

    // fork: convert down-proj weights concurrently with GEMM1
    cudaEventRecord(ev1, 0);
    cudaStreamWaitEvent(s2, ev1, 0);
    cvt_kernel<<<4096, 256, 0, s2>>>((const float4*)dn, dn16, E_ * I_ * H_ / 4);
    cudaEventRecord(ev2, s2);

    moe_gemm<2048, true><<<dim3(8, 6, E_), 256, SMEM_BYTES>>>(hs16c, gupc);

    // join before GEMM2
    cudaStreamWaitEvent(0, ev2, 0);
    moe_gemm<768, false><<<dim3(8, 8, E_), 256, SMEM_BYTES>>>(nullptr, dnc);

    combine_kernel<<<(T_ * H_ / 4 + 255) / 256, 256>>>((float4*)out);
}

// round 13
// speedup vs baseline: 1.6648x; 1.3127x over previous
#include <cuda_runtime.h>
#include <cuda_fp16.h>
#include <cstdint>

static constexpr int E_   = 32;
static constexpr int H_   = 2048;
static constexpr int I_   = 768;
static constexpr int T_   = 2048;
static constexpr int MAXA = 8192;

// ---------------- scratch ----------------------------------------------------
__device__ int   g_counts[E_];
__device__ int   g_offsets[E_];
__device__ int   g_total;
__device__ int   g_tok[MAXA];
__device__ float g_w[MAXA];
__device__ int   g_inv[T_ * 4];
__device__ __align__(16) __half g_hs16[(size_t)T_ * H_];
__device__ __align__(16) __half g_act16[(size_t)MAXA * I_];
__device__ __align__(16) __half g_dout16[(size_t)MAXA * H_];

__device__ __forceinline__ uint32_t smem_u32(const void* p) {
    uint32_t a;
    asm("{ .reg .u64 t; cvta.to.shared.u64 t, %1; cvt.u32.u64 %0, t; }" : "=r"(a) : "l"(p));
    return a;
}
__device__ __forceinline__ void cpa16(uint32_t dst, const void* src) {
    asm volatile("cp.async.cg.shared.global [%0], [%1], 16;" :: "r"(dst), "l"(src));
}
__device__ __forceinline__ uint32_t pk2(float a, float b) {
    __half2 h = __floats2half2_rn(a, b);
    return *reinterpret_cast<uint32_t*>(&h);
}

// ---------------- fp32 -> fp16 streaming convert (hidden states only) ----------
__global__ void cvt_kernel(const float4* __restrict__ in, __half2* __restrict__ out, int n4) {
    for (int i = blockIdx.x * blockDim.x + threadIdx.x; i < n4;
         i += gridDim.x * blockDim.x) {
        float4 v = in[i];
        out[2 * i]     = __floats2half2_rn(v.x, v.y);
        out[2 * i + 1] = __floats2half2_rn(v.z, v.w);
    }
}

// ---------------- routing (known-good) ----------------------------------------
__global__ void route_kernel(const int* __restrict__ ridx,
                             const float* __restrict__ rw) {
    __shared__ int s_cnt[E_], s_cur[E_], s_off[E_];
    int tid = threadIdx.x;
    if (tid < E_) { s_cnt[tid] = 0; s_cur[tid] = 0; }
    __syncthreads();
    for (int t = tid; t < T_; t += blockDim.x) {
        int e0 = ridx[4*t], e1 = ridx[4*t+1], e2 = ridx[4*t+2], e3 = ridx[4*t+3];
        if (e0 != e1 && e0 != e2 && e0 != e3) atomicAdd(&s_cnt[e0], 1);
        if (e1 != e2 && e1 != e3)             atomicAdd(&s_cnt[e1], 1);
        if (e2 != e3)                          atomicAdd(&s_cnt[e2], 1);
        atomicAdd(&s_cnt[e3], 1);
    }
    __syncthreads();
    if (tid == 0) {
        int acc = 0;
        for (int e = 0; e < E_; e++) {
            s_off[e] = acc; g_offsets[e] = acc; g_counts[e] = s_cnt[e];
            acc += s_cnt[e];
        }
        g_total = acc;
    }
    __syncthreads();
    for (int t = tid; t < T_; t += blockDim.x) {
        int ee[4]; float ww[4];
        #pragma unroll
        for (int k = 0; k < 4; k++) { ee[k] = ridx[4*t+k]; ww[k] = rw[4*t+k]; }
        #pragma unroll
        for (int k = 0; k < 4; k++) {
            bool keep = true;
            #pragma unroll
            for (int j = k + 1; j < 4; j++) if (ee[j] == ee[k]) keep = false;
            int pos = -1;
            if (keep) {
                pos = s_off[ee[k]] + atomicAdd(&s_cur[ee[k]], 1);
                g_tok[pos] = t; g_w[pos] = ww[k];
            }
            g_inv[4*t + k] = pos;
        }
    }
}

// ---------------- fp16 grouped GEMM, fp32 B converted in-kernel ---------------
// 128x256 tile, 8 warps 64x64, k-chunk 32. A: cp.async fp16 4-stage.
// B: LDG fp32 -> cvt -> STS fp16, double-buffered, reg-staged one chunk ahead.
static constexpr int A_PITCH = 80;                   // 32 fp16 = 64 B + 16 pad
static constexpr int A_STG   = 128 * A_PITCH;        // 10240
static constexpr int A_TOTAL = 4 * A_STG;            // 40960
static constexpr int B_PITCH = 528;                  // 256 fp16 = 512 B + 16 pad
static constexpr int B_BUF   = 32 * B_PITCH;         // 16896
static constexpr int SMEM_BYTES = A_TOTAL + 2 * B_BUF;  // 74752

template<int KDIM, bool FIRST>
__global__ void __launch_bounds__(256, 1)
moe_gemm(const __half* __restrict__ Ain, const float* __restrict__ Bfp32) {
    constexpr int NCH    = KDIM / 32;
    constexpr int LDB    = FIRST ? 1536 : 2048;
    constexpr int ROWSPE = FIRST ? 2048 : 768;
    constexpr int NOUT   = FIRST ? 128 : 256;

    extern __shared__ uint8_t smraw[];
    const int e   = blockIdx.z;
    const int cnt = g_counts[e];
    const int m0  = blockIdx.x * 128;
    if (m0 >= cnt) return;
    const int off = g_offsets[e];
    const int n0  = blockIdx.y * NOUT;
    const int tid = threadIdx.x;
    const int wid = tid >> 5, lane = tid & 31;
    const uint32_t sbase = smem_u32(smraw);

    // ---- A staging: row = tid>>1 (0..127), seg = tid&1 (32 B each) ----
    const int a_r = tid >> 1;
    const int a_s = tid & 1;
    {
        // computed below after pointer setup
    }
    int gmA = m0 + a_r;
    int rrA = (gmA < cnt) ? gmA : 0;
    const __half* aSrc = (FIRST ? Ain + (size_t)g_tok[off + rrA] * KDIM
                                : g_act16 + (size_t)(off + rrA) * KDIM) + a_s * 16;
    const uint32_t aDst = sbase + (uint32_t)(a_r * A_PITCH + a_s * 32);

    // ---- B staging: row = tid>>3 (0..31), seg s = tid&7 ----
    const int b_r = tid >> 3;
    const int b_s = tid & 7;
    const float* bColBase[4];
    #pragma unroll
    for (int j = 0; j < 4; j++) {
        int c8 = 8 * b_s + 64 * j;          // fp16 col position within 256
        int gc = FIRST ? (c8 < 128 ? n0 + c8 : 768 + n0 + (c8 - 128))
                       : n0 + c8;
        bColBase[j] = Bfp32 + ((size_t)e * ROWSPE + b_r) * LDB + gc;
    }
    const uint32_t bDstBase = sbase + A_TOTAL + (uint32_t)(b_r * B_PITCH + b_s * 16);

    float4 breg[8];
    auto ldg_b = [&](int c) {
        const size_t roff = (size_t)c * 32 * LDB;
        #pragma unroll
        for (int j = 0; j < 4; j++) {
            breg[2 * j]     = *(const float4*)(bColBase[j] + roff);
            breg[2 * j + 1] = *(const float4*)(bColBase[j] + roff + 4);
        }
    };
    auto sts_b = [&](int c) {
        uint32_t dst = bDstBase + (uint32_t)(c & 1) * B_BUF;
        #pragma unroll
        for (int j = 0; j < 4; j++) {
            uint32_t h0 = pk2(breg[2*j].x,   breg[2*j].y);
            uint32_t h1 = pk2(breg[2*j].z,   breg[2*j].w);
            uint32_t h2 = pk2(breg[2*j+1].x, breg[2*j+1].y);
            uint32_t h3 = pk2(breg[2*j+1].z, breg[2*j+1].w);
            asm volatile("st.shared.v4.b32 [%0], {%1,%2,%3,%4};"
                         :: "r"(dst + (uint32_t)(j * 128)),
                            "r"(h0), "r"(h1), "r"(h2), "r"(h3) : "memory");
        }
    };
    auto cp_a = [&](int c) {
        const uint32_t so = (uint32_t)(c & 3) * A_STG;
        const __half* src = aSrc + (size_t)c * 32;
        cpa16(aDst + so, src);
        cpa16(aDst + so + 16, src + 8);
        asm volatile("cp.async.commit_group;" ::: "memory");
    };

    float acc[4][8][4];
    #pragma unroll
    for (int i = 0; i < 4; i++)
        #pragma unroll
        for (int j = 0; j < 8; j++)
            #pragma unroll
            for (int k = 0; k < 4; k++) acc[i][j][k] = 0.f;

    const int wm = (wid >> 2) * 64;
    const int wn = (wid & 3) * (FIRST ? 32 : 64);
    const int qr = lane >> 2;
    const int qk = lane & 3;

    const uint32_t a_lm_off = (uint32_t)((wm + (lane & 15)) * A_PITCH + (lane >> 4) * 16);
    const uint32_t b_lm_krow = (uint32_t)((lane & 7) + ((lane >> 3) & 1) * 8);
    const uint32_t b_lm_noff = (uint32_t)((lane >> 4) * 8 * 2);

    // ---- prologue ----
    ldg_b(0);
    cp_a(0); cp_a(1); cp_a(2);
    sts_b(0);
    ldg_b(1);

    for (int c = 0; c < NCH; c++) {
        int rem = NCH - 1 - c;
        if (rem >= 2)      asm volatile("cp.async.wait_group 2;" ::: "memory");
        else if (rem == 1) asm volatile("cp.async.wait_group 1;" ::: "memory");
        else               asm volatile("cp.async.wait_group 0;" ::: "memory");
        __syncthreads();
        if (c + 3 < NCH) cp_a(c + 3);

        const uint32_t sA = sbase + (uint32_t)(c & 3) * A_STG;
        const uint32_t sB = sbase + A_TOTAL + (uint32_t)(c & 1) * B_BUF;
        #pragma unroll
        for (int kk = 0; kk < 32; kk += 16) {
            uint32_t af[4][4], bf[8][2];
            #pragma unroll
            for (int mi = 0; mi < 4; mi++) {
                uint32_t addr = sA + a_lm_off + (uint32_t)(mi * 16 * A_PITCH + kk * 2);
                asm volatile(
                    "ldmatrix.sync.aligned.m8n8.x4.shared.b16 {%0,%1,%2,%3}, [%4];"
                    : "=r"(af[mi][0]), "=r"(af[mi][1]),
                      "=r"(af[mi][2]), "=r"(af[mi][3])
                    : "r"(addr));
            }
            #pragma unroll
            for (int nip = 0; nip < 4; nip++) {
                int ni = 2 * nip;
                int nb = FIRST ? (ni < 4 ? wn + ni * 8 : 128 + wn + (ni - 4) * 8)
                               : wn + ni * 8;
                uint32_t addr = sB + (kk + b_lm_krow) * B_PITCH
                                   + (uint32_t)(nb * 2) + b_lm_noff;
                asm volatile(
                    "ldmatrix.sync.aligned.m8n8.x4.trans.shared.b16 {%0,%1,%2,%3}, [%4];"
                    : "=r"(bf[ni][0]), "=r"(bf[ni][1]),
                      "=r"(bf[ni + 1][0]), "=r"(bf[ni + 1][1])
                    : "r"(addr));
            }
            #pragma unroll
            for (int mi = 0; mi < 4; mi++)
                #pragma unroll
                for (int ni = 0; ni < 8; ni++)
                    asm volatile(
                        "mma.sync.aligned.m16n8k16.row.col.f32.f16.f16.f32 "
                        "{%0,%1,%2,%3}, {%4,%5,%6,%7}, {%8,%9}, {%0,%1,%2,%3};"
                        : "+f"(acc[mi][ni][0]), "+f"(acc[mi][ni][1]),
                          "+f"(acc[mi][ni][2]), "+f"(acc[mi][ni][3])
                        : "r"(af[mi][0]), "r"(af[mi][1]),
                          "r"(af[mi][2]), "r"(af[mi][3]),
                          "r"(bf[ni][0]), "r"(bf[ni][1]));
        }
        if (c + 1 < NCH) {
            sts_b(c + 1);                  // opposite buffer; safe per barrier
            if (c + 2 < NCH) ldg_b(c + 2); // in flight during next chunk's MMA
        }
    }
    __syncthreads();

    // ---- epilogue ----
    #pragma unroll
    for (int mi = 0; mi < 4; mi++) {
        #pragma unroll
        for (int half = 0; half < 2; half++) {
            int r  = wm + mi * 16 + qr + half * 8;
            int gm = m0 + r;
            if (gm >= cnt) continue;
            if (FIRST) {
                __half* rowp = g_act16 + (size_t)(off + gm) * I_ + n0;
                #pragma unroll
                for (int ni = 0; ni < 4; ni++) {
                    int nc = wn + ni * 8 + qk * 2;
                    float g0 = acc[mi][ni][half * 2 + 0];
                    float g1 = acc[mi][ni][half * 2 + 1];
                    float u0 = acc[mi][ni + 4][half * 2 + 0];
                    float u1 = acc[mi][ni + 4][half * 2 + 1];
                    float v0 = u0 * (g0 / (1.f + __expf(-g0)));
                    float v1 = u1 * (g1 / (1.f + __expf(-g1)));
                    *(__half2*)(rowp + nc) = __floats2half2_rn(v0, v1);
                }
            } else {
                float w = g_w[off + gm];
                __half* rowp = g_dout16 + (size_t)(off + gm) * H_ + n0;
                #pragma unroll
                for (int ni = 0; ni < 8; ni++) {
                    int nc = wn + ni * 8 + qk * 2;
                    *(__half2*)(rowp + nc) =
                        __floats2half2_rn(acc[mi][ni][half * 2 + 0] * w,
                                          acc[mi][ni][half * 2 + 1] * w);
                }
            }
        }
    }
}

// ---------------- combine: fp16 dout -> fp32 out --------------------------------
__global__ void combine_kernel(float4* __restrict__ out) {
    int idx = blockIdx.x * blockDim.x + threadIdx.x;
    if (idx >= T_ * H_ / 4) return;
    int t  = idx >> 9;
    int h4 = idx & 511;
    float4 s = make_float4(0.f, 0.f, 0.f, 0.f);
    #pragma unroll
    for (int k = 0; k < 4; k++) {
        int pos = g_inv[4 * t + k];
        if (pos >= 0) {
            const __half2* p = (const __half2*)(g_dout16 + (size_t)pos * H_ + h4 * 4);
            float2 a = __half22float2(p[0]);
            float2 b = __half22float2(p[1]);
            s.x += a.x; s.y += a.y; s.z += b.x; s.w += b.y;
        }
    }
    out[idx] = s;
}

// ---------------- launch --------------------------------------------------------
extern "C" void kernel_launch(void* const* d_in, const int* in_sizes, int n_in,
                              void* d_out, int out_size) {
    const float* hs  = (const float*)d_in[0];
    const float* rw  = (const float*)d_in[1];
    const int*   ri  = (const int*)d_in[2];
    const float* gup = (const float*)d_in[4];
    const float* dn  = (const float*)d_in[5];
    float* out = (float*)d_out;

    cudaFuncSetAttribute((const void*)moe_gemm<2048, true>,
                         cudaFuncAttributeMaxDynamicSharedMemorySize, SMEM_BYTES);
    cudaFuncSetAttribute((const void*)moe_gemm<768, false>,
                         cudaFuncAttributeMaxDynamicSharedMemorySize, SMEM_BYTES);

    __half2* hs16; cudaGetSymbolAddress((void**)&hs16, g_hs16);
    const __half* hs16c = (const __half*)hs16;

    route_kernel<<<1, 256>>>(ri, rw);
    cvt_kernel<<<1024, 256>>>((const float4*)hs, hs16, T_ * H_ / 4);

    // x = m-tile (fastest), y = n-tile, z = expert
    moe_gemm<2048, true><<<dim3(8, 6, E_), 256, SMEM_BYTES>>>(hs16c, gup);
    moe_gemm<768, false><<<dim3(8, 8, E_), 256, SMEM_BYTES>>>(nullptr, dn);

    combine_kernel<<<(T_ * H_ / 4 + 255) / 256, 256>>>((float4*)out);
}